// round 12
// baseline (speedup 1.0000x reference)
#include <cuda_runtime.h>
#include <cuda_fp16.h>
#include <cstdint>

// Problem constants
#define NB 16
#define CH 64
#define LL 4096   // H*W
#define DD 1024   // pooled locations
#define CK 8      // C>>3 (theta/phi channels)
#define CG 32     // C>>1 (g channels)

typedef unsigned long long ull;

// Scratch (device globals):
//  g_thetaH[n][l][q]  u32 = f16x2 {theta[2q], theta[2q+1]}, pre-scaled by log2(e)
//  g_phiP  [n][4096]  u32, phi fused-B layout: idx = s*64 + gr*8 + q*2 + u
//  g_gH    [n][j][s*4+q][elem] f16, elem -> d = 16s + {2q,2q+1,2q+8,2q+9}
__device__ __align__(16) uint32_t g_thetaH[NB * LL * 4];   // 4 MB
__device__ __align__(16) uint32_t g_phiP[NB * 4096];       // 256 KB
__device__ __align__(16) __half   g_gH[NB * CG * 1024];    // 1 MB

__device__ __forceinline__ ull pk2(float a, float b) {
    ull r; asm("mov.b64 %0, {%1, %2};" : "=l"(r) : "f"(a), "f"(b)); return r;
}
__device__ __forceinline__ float2 upk2(ull v) {
    float2 r; asm("mov.b64 {%0, %1}, %2;" : "=f"(r.x), "=f"(r.y) : "l"(v)); return r;
}
__device__ __forceinline__ ull fma2(ull a, ull b, ull c) {
    ull d; asm("fma.rn.f32x2 %0, %1, %2, %3;" : "=l"(d) : "l"(a), "l"(b), "l"(c)); return d;
}
__device__ __forceinline__ uint32_t pack_h2(float lo, float hi) {
    uint32_t r; asm("cvt.rn.f16x2.f32 %0, %1, %2;" : "=r"(r) : "f"(hi), "f"(lo)); return r;
}
__device__ __forceinline__ uint32_t ex2h2(uint32_t h) {
    uint32_t r; asm("ex2.approx.f16x2 %0, %1;" : "=r"(r) : "r"(h)); return r;
}

// MMA1: m16n8k8 f16 with f16 accumulator (C=0).
__device__ __forceinline__ void mma_k8_h(uint32_t* d, uint32_t a0, uint32_t a1,
                                         uint32_t b0) {
    asm volatile(
        "mma.sync.aligned.m16n8k8.row.col.f16.f16.f16.f16 "
        "{%0,%1}, {%2,%3}, {%4}, {%5,%6};"
        : "=r"(d[0]), "=r"(d[1])
        : "r"(a0), "r"(a1), "r"(b0), "r"(0u), "r"(0u));
}
// MMA2: m16n8k16 f16, f32 accumulate
__device__ __forceinline__ void mma_k16(float* c, uint32_t a0, uint32_t a1,
                                        uint32_t a2, uint32_t a3,
                                        uint32_t b0, uint32_t b1) {
    asm volatile(
        "mma.sync.aligned.m16n8k16.row.col.f32.f16.f16.f32 "
        "{%0,%1,%2,%3}, {%4,%5,%6,%7}, {%8,%9}, {%0,%1,%2,%3};"
        : "+f"(c[0]), "+f"(c[1]), "+f"(c[2]), "+f"(c[3])
        : "r"(a0), "r"(a1), "r"(a2), "r"(a3), "r"(b0), "r"(b1));
}

// ---------------------------------------------------------------------------
// Fused projection kernel (exactly the R8 version — fastest measured).
// ---------------------------------------------------------------------------
__global__ void __launch_bounds__(256) proj_fused_kernel(
        const float* __restrict__ x, const float* __restrict__ w_theta,
        const float* __restrict__ w_phi, const float* __restrict__ w_g) {
    __shared__ ull wt2[CH * 4];
    __shared__ ull wp2[CH * 4];
    __shared__ ull wg2[CH * 16];
    int tid = threadIdx.x;
    for (int i = tid; i < CH * 4; i += 256) {
        int kp = i & 3, c = i >> 2;
        wt2[i] = pk2(w_theta[(2 * kp) * CH + c] * 1.4426950408889634f,
                     w_theta[(2 * kp + 1) * CH + c] * 1.4426950408889634f);
        wp2[i] = pk2(w_phi[(2 * kp) * CH + c], w_phi[(2 * kp + 1) * CH + c]);
    }
    for (int i = tid; i < CH * 16; i += 256) {
        int jp = i & 15, c = i >> 4;
        wg2[i] = pk2(w_g[(2 * jp) * CH + c], w_g[(2 * jp + 1) * CH + c]);
    }
    __syncthreads();

    int bid = blockIdx.x;
    int n = bid >> 4, yt = bid & 15;
    int b0 = tid & 1, b1 = (tid >> 1) & 1;
    int xpair = (tid >> 2) & 31;
    int yp = tid >> 7;
    int y = yt * 4 + yp * 2 + b1;
    int xc = xpair * 2 + b0;
    int l = y * 64 + xc;

    const float* xp = x + ((size_t)n * CH) * LL + l;

    ull at[4], ap[4], ag[16];
#pragma unroll
    for (int i = 0; i < 4; i++) { at[i] = 0ull; ap[i] = 0ull; }
#pragma unroll
    for (int i = 0; i < 16; i++) ag[i] = 0ull;

#pragma unroll 8
    for (int c = 0; c < CH; c++) {
        float xv = xp[(size_t)c * LL];
        ull vd = pk2(xv, xv);
#pragma unroll
        for (int kp = 0; kp < 4; kp++) at[kp] = fma2(wt2[c * 4 + kp], vd, at[kp]);
#pragma unroll
        for (int kp = 0; kp < 4; kp++) ap[kp] = fma2(wp2[c * 4 + kp], vd, ap[kp]);
#pragma unroll
        for (int jp = 0; jp < 16; jp++) ag[jp] = fma2(wg2[c * 16 + jp], vd, ag[jp]);
    }

    {
        float2 t0 = upk2(at[0]), t1 = upk2(at[1]), t2 = upk2(at[2]), t3 = upk2(at[3]);
        uint4 tq;
        tq.x = pack_h2(t0.x, t0.y);
        tq.y = pack_h2(t1.x, t1.y);
        tq.z = pack_h2(t2.x, t2.y);
        tq.w = pack_h2(t3.x, t3.y);
        *(uint4*)(g_thetaH + ((size_t)n * LL + l) * 4) = tq;
    }

    float phv[CK], gv[CG];
#pragma unroll
    for (int kp = 0; kp < 4; kp++) {
        float2 v = upk2(ap[kp]); phv[2 * kp] = v.x; phv[2 * kp + 1] = v.y;
    }
#pragma unroll
    for (int jp = 0; jp < 16; jp++) {
        float2 v = upk2(ag[jp]); gv[2 * jp] = v.x; gv[2 * jp + 1] = v.y;
    }
#pragma unroll
    for (int k = 0; k < CK; k++) {
        float v = phv[k];
        v = fmaxf(v, __shfl_xor_sync(0xffffffffu, v, 1));
        v = fmaxf(v, __shfl_xor_sync(0xffffffffu, v, 2));
        phv[k] = v;
    }
#pragma unroll
    for (int j = 0; j < CG; j++) {
        float v = gv[j];
        v = fmaxf(v, __shfl_xor_sync(0xffffffffu, v, 1));
        v = fmaxf(v, __shfl_xor_sync(0xffffffffu, v, 2));
        gv[j] = v;
    }

    if ((tid & 3) == 0) {
        int d = (yt * 2 + yp) * 32 + xpair;
        int s = d >> 4, gr = d & 7, u = (d >> 3) & 1;
        uint32_t* pdst = g_phiP + (size_t)n * 4096 + s * 64 + gr * 8 + u;
        pdst[0] = pack_h2(phv[0], phv[1]);
        pdst[2] = pack_h2(phv[2], phv[3]);
        pdst[4] = pack_h2(phv[4], phv[5]);
        pdst[6] = pack_h2(phv[6], phv[7]);

        int xu = (xpair >> 3) & 1;
        int qf = (xpair & 7) >> 1;
        int rb = xpair & 1;
        int elem = xu * 2 + rb;
        __half* gdst = g_gH + (size_t)n * CG * 1024;
#pragma unroll
        for (int j = 0; j < CG; j++)
            gdst[(j * 256 + s * 4 + qf) * 4 + elem] = __float2half_rn(gv[j]);
    }
}

// ---------------------------------------------------------------------------
// Attention kernel: tensor-core flash, M=32 per warp, STAGE-PIPELINED:
// logits+exp of iter s+1 overlap the MMA2 batch of iter s.
// Grid (8 L-tiles, 16 n) x 512 threads = 128 CTAs, single wave.
// smem: phi 16K | gA 32.5K | gB 32.5K | wof 5K = 88064 B
// ---------------------------------------------------------------------------
#define SM_PHI 0
#define SM_GA  16384
#define SM_GB  49664
#define SM_WOF 82944
#define SMEM_SZ 88064

#define ONES_H2 0x3C003C00u   // f16x2 {1.0, 1.0}

__global__ void __launch_bounds__(512, 1) attn_kernel(
        const float* __restrict__ x, const float* __restrict__ w_o,
        const float* __restrict__ gammap, float* __restrict__ out) {
    extern __shared__ char smem[];
    uint32_t* wof = (uint32_t*)(smem + SM_WOF);

    int tid = threadIdx.x;
    int n = blockIdx.y;
    int l0 = blockIdx.x * 512;
    float gamma = *gammap;

    // Cooperative fills
    {
        const uint4* s1 = (const uint4*)(g_phiP + (size_t)n * 4096);
        uint4* d1 = (uint4*)(smem + SM_PHI);
        for (int i = tid; i < 1024; i += 512) d1[i] = s1[i];
        const ull* s2 = (const ull*)(g_gH + (size_t)n * CG * 1024);
        ull* gA = (ull*)(smem + SM_GA);
        ull* gB = (ull*)(smem + SM_GB);
        for (int i = tid; i < 8192; i += 512) {
            ull v = s2[i];
            int j = i >> 8, sq = i & 255;
            int gr = j & 7, half = (j >> 3) & 1;
            ull* arr = (j < 16) ? gA : gB;
            arr[(gr * 260 + sq) * 2 + half] = v;
        }
        const float2* s3 = (const float2*)w_o;
        for (int i = tid; i < 1024; i += 512) {
            int oc = i >> 4, kq = i & 15;
            float2 w = s3[oc * 16 + kq];
            wof[oc * 20 + kq] = pack_h2(w.x * gamma, w.y * gamma);
        }
    }

    int warp = tid >> 5, lane = tid & 31;
    int gr = lane >> 2, q = lane & 3;
    int rXa = warp * 32 + gr;     // X block rows: rXa, rXa+8
    int rYa = rXa + 16;           // Y block rows: rYa, rYa+8

    const uint32_t* tbase = g_thetaH + ((size_t)n * LL + l0) * 4 + q;
    uint32_t tXa = tbase[(size_t)rXa * 4];
    uint32_t tXb = tbase[(size_t)(rXa + 8) * 4];
    uint32_t tYa = tbase[(size_t)rYa * 4];
    uint32_t tYb = tbase[(size_t)(rYa + 8) * 4];
    __syncthreads();

    float c0[4], c1[4], c2[4], c3[4], c4[4];   // X accumulators
    float d0[4], d1[4], d2a[4], d3[4], d4[4];  // Y accumulators
#pragma unroll
    for (int i = 0; i < 4; i++) {
        c0[i] = 0.f; c1[i] = 0.f; c2[i] = 0.f; c3[i] = 0.f; c4[i] = 0.f;
        d0[i] = 0.f; d1[i] = 0.f; d2a[i] = 0.f; d3[i] = 0.f; d4[i] = 0.f;
    }

    const char* phiPtr = smem + SM_PHI + (gr * 8 + q * 2) * 4;
    const char* gaPtr  = smem + SM_GA + (gr * 260 + q) * 16;
    const char* gbPtr  = smem + SM_GB + (gr * 260 + q) * 16;

    // --- pipeline preamble: logits+exp for s=0, g for s=0 ---
    uint32_t aq0, aq1, aq2, aq3, aq4, aq5, aq6, aq7;
    {
        ull pv0 = *(const ull*)phiPtr;
        uint32_t h0[2], h1[2], h2[2], h3[2];
        mma_k8_h(h0, tXa, tXb, (uint32_t)pv0);
        mma_k8_h(h1, tXa, tXb, (uint32_t)(pv0 >> 32));
        mma_k8_h(h2, tYa, tYb, (uint32_t)pv0);
        mma_k8_h(h3, tYa, tYb, (uint32_t)(pv0 >> 32));
        aq0 = ex2h2(h0[0]); aq1 = ex2h2(h0[1]);
        aq2 = ex2h2(h1[0]); aq3 = ex2h2(h1[1]);
        aq4 = ex2h2(h2[0]); aq5 = ex2h2(h2[1]);
        aq6 = ex2h2(h3[0]); aq7 = ex2h2(h3[1]);
    }
    ulonglong2 ga = *(const ulonglong2*)gaPtr;
    ulonglong2 gb = *(const ulonglong2*)gbPtr;

#pragma unroll 2
    for (int s = 0; s < 64; s++) {
        // ---- stage A(s+1): logits (s=63 overreads into gA region: discarded) ----
        phiPtr += 256;
        ull pvn = *(const ull*)phiPtr;
        uint32_t h0[2], h1[2], h2[2], h3[2];
        mma_k8_h(h0, tXa, tXb, (uint32_t)pvn);
        mma_k8_h(h1, tXa, tXb, (uint32_t)(pvn >> 32));
        mma_k8_h(h2, tYa, tYb, (uint32_t)pvn);
        mma_k8_h(h3, tYa, tYb, (uint32_t)(pvn >> 32));

        // g prefetch for s+1
        gaPtr += 64; gbPtr += 64;
        ulonglong2 gan = *(const ulonglong2*)gaPtr;
        ulonglong2 gbn = *(const ulonglong2*)gbPtr;

        // ---- stage B(s): MMA2 batch with a(s) (tensor pipe busy) ----
        mma_k16(c0, aq0, aq1, aq2, aq3, (uint32_t)ga.x, (uint32_t)(ga.x >> 32));
        mma_k16(c1, aq0, aq1, aq2, aq3, (uint32_t)ga.y, (uint32_t)(ga.y >> 32));
        mma_k16(c2, aq0, aq1, aq2, aq3, (uint32_t)gb.x, (uint32_t)(gb.x >> 32));
        mma_k16(c3, aq0, aq1, aq2, aq3, (uint32_t)gb.y, (uint32_t)(gb.y >> 32));
        mma_k16(c4, aq0, aq1, aq2, aq3, ONES_H2, ONES_H2);
        mma_k16(d0, aq4, aq5, aq6, aq7, (uint32_t)ga.x, (uint32_t)(ga.x >> 32));
        mma_k16(d1, aq4, aq5, aq6, aq7, (uint32_t)ga.y, (uint32_t)(ga.y >> 32));
        mma_k16(d2a, aq4, aq5, aq6, aq7, (uint32_t)gb.x, (uint32_t)(gb.x >> 32));
        mma_k16(d3, aq4, aq5, aq6, aq7, (uint32_t)gb.y, (uint32_t)(gb.y >> 32));
        mma_k16(d4, aq4, aq5, aq6, aq7, ONES_H2, ONES_H2);

        // ---- exp for s+1 (MUFU, overlaps MMA2 drain) ----
        aq0 = ex2h2(h0[0]); aq1 = ex2h2(h0[1]);
        aq2 = ex2h2(h1[0]); aq3 = ex2h2(h1[1]);
        aq4 = ex2h2(h2[0]); aq5 = ex2h2(h2[1]);
        aq6 = ex2h2(h3[0]); aq7 = ex2h2(h3[1]);

        ga = gan; gb = gbn;
    }

    float invXa = 1.0f / c4[0], invXb = 1.0f / c4[2];
    float invYa = 1.0f / d4[0], invYb = 1.0f / d4[2];

    // epilogue A-fragments (k = j), X then Y
    uint32_t eX0 = pack_h2(c0[0] * invXa, c0[1] * invXa);
    uint32_t eX1 = pack_h2(c0[2] * invXb, c0[3] * invXb);
    uint32_t eX2 = pack_h2(c1[0] * invXa, c1[1] * invXa);
    uint32_t eX3 = pack_h2(c1[2] * invXb, c1[3] * invXb);
    uint32_t eX4 = pack_h2(c2[0] * invXa, c2[1] * invXa);
    uint32_t eX5 = pack_h2(c2[2] * invXb, c2[3] * invXb);
    uint32_t eX6 = pack_h2(c3[0] * invXa, c3[1] * invXa);
    uint32_t eX7 = pack_h2(c3[2] * invXb, c3[3] * invXb);
    uint32_t eY0 = pack_h2(d0[0] * invYa, d0[1] * invYa);
    uint32_t eY1 = pack_h2(d0[2] * invYb, d0[3] * invYb);
    uint32_t eY2 = pack_h2(d1[0] * invYa, d1[1] * invYa);
    uint32_t eY3 = pack_h2(d1[2] * invYb, d1[3] * invYb);
    uint32_t eY4 = pack_h2(d2a[0] * invYa, d2a[1] * invYa);
    uint32_t eY5 = pack_h2(d2a[2] * invYb, d2a[3] * invYb);
    uint32_t eY6 = pack_h2(d3[0] * invYa, d3[1] * invYa);
    uint32_t eY7 = pack_h2(d3[2] * invYb, d3[3] * invYb);

    const uint32_t* wrow = wof + gr * 20;
#pragma unroll
    for (int ob = 0; ob < 8; ob++) {
        uint32_t b00 = wrow[ob * 160 + q];
        uint32_t b01 = wrow[ob * 160 + q + 4];
        uint32_t b10 = wrow[ob * 160 + q + 8];
        uint32_t b11 = wrow[ob * 160 + q + 12];

        float fX[4] = {0.f, 0.f, 0.f, 0.f};
        mma_k16(fX, eX0, eX1, eX2, eX3, b00, b01);
        mma_k16(fX, eX4, eX5, eX6, eX7, b10, b11);
        float fY[4] = {0.f, 0.f, 0.f, 0.f};
        mma_k16(fY, eY0, eY1, eY2, eY3, b00, b01);
        mma_k16(fY, eY4, eY5, eY6, eY7, b10, b11);

        int oc = ob * 8 + 2 * q;
        const float* px = x + ((size_t)n * CH + oc) * LL + l0 + rXa;
        float* po = out + ((size_t)n * CH + oc) * LL + l0 + rXa;
        po[0]       = px[0]       + fX[0];
        po[LL]      = px[LL]      + fX[1];
        po[8]       = px[8]       + fX[2];
        po[LL + 8]  = px[LL + 8]  + fX[3];
        po[16]      = px[16]      + fY[0];
        po[LL + 16] = px[LL + 16] + fY[1];
        po[24]      = px[24]      + fY[2];
        po[LL + 24] = px[LL + 24] + fY[3];
    }
}

// ---------------------------------------------------------------------------
extern "C" void kernel_launch(void* const* d_in, const int* in_sizes, int n_in,
                              void* d_out, int out_size) {
    const float* x       = (const float*)d_in[0];
    const float* w_theta = (const float*)d_in[1];
    const float* w_phi   = (const float*)d_in[2];
    const float* w_g     = (const float*)d_in[3];
    const float* w_o     = (const float*)d_in[4];
    const float* gammap  = (const float*)d_in[5];
    float* out = (float*)d_out;

    cudaFuncSetAttribute(attn_kernel, cudaFuncAttributeMaxDynamicSharedMemorySize,
                         SMEM_SZ);

    proj_fused_kernel<<<256, 256>>>(x, w_theta, w_phi, w_g);
    dim3 grid(8, NB);
    attn_kernel<<<grid, 512, SMEM_SZ>>>(x, w_o, gammap, out);
}

// round 13
// speedup vs baseline: 1.0397x; 1.0397x over previous
#include <cuda_runtime.h>
#include <cuda_fp16.h>
#include <cstdint>

// Problem constants
#define NB 16
#define CH 64
#define LL 4096   // H*W
#define DD 1024   // pooled locations
#define CK 8      // C>>3 (theta/phi channels)
#define CG 32     // C>>1 (g channels)

typedef unsigned long long ull;

// Scratch (device globals):
//  g_thetaH[n][l][q]  u32 = f16x2 {theta[2q], theta[2q+1]}, pre-scaled by log2(e)
//  g_phiP  [n][4096]  u32, phi fused-B layout: idx = s*64 + gr*8 + q*2 + u
//  g_gH    [n][j][s*4+q][elem] f16, elem -> d = 16s + {2q,2q+1,2q+8,2q+9}
__device__ __align__(16) uint32_t g_thetaH[NB * LL * 4];   // 4 MB
__device__ __align__(16) uint32_t g_phiP[NB * 4096];       // 256 KB
__device__ __align__(16) __half   g_gH[NB * CG * 1024];    // 1 MB

__device__ __forceinline__ ull pk2(float a, float b) {
    ull r; asm("mov.b64 %0, {%1, %2};" : "=l"(r) : "f"(a), "f"(b)); return r;
}
__device__ __forceinline__ float2 upk2(ull v) {
    float2 r; asm("mov.b64 {%0, %1}, %2;" : "=f"(r.x), "=f"(r.y) : "l"(v)); return r;
}
__device__ __forceinline__ ull fma2(ull a, ull b, ull c) {
    ull d; asm("fma.rn.f32x2 %0, %1, %2, %3;" : "=l"(d) : "l"(a), "l"(b), "l"(c)); return d;
}
__device__ __forceinline__ uint32_t pack_h2(float lo, float hi) {
    uint32_t r; asm("cvt.rn.f16x2.f32 %0, %1, %2;" : "=r"(r) : "f"(hi), "f"(lo)); return r;
}
__device__ __forceinline__ uint32_t ex2h2(uint32_t h) {
    uint32_t r; asm("ex2.approx.f16x2 %0, %1;" : "=r"(r) : "r"(h)); return r;
}
__device__ __forceinline__ uint32_t hadd2u(uint32_t a, uint32_t b) {
    uint32_t r; asm("add.f16x2 %0, %1, %2;" : "=r"(r) : "r"(a), "r"(b)); return r;
}
__device__ __forceinline__ float h2sum(uint32_t h) {
    __half2 v = *(__half2*)&h;
    float2 f = __half22float2(v);
    return f.x + f.y;
}

// MMA1: m16n8k8 f16 with f16 accumulator (C=0).
__device__ __forceinline__ void mma_k8_h(uint32_t* d, uint32_t a0, uint32_t a1,
                                         uint32_t b0) {
    asm volatile(
        "mma.sync.aligned.m16n8k8.row.col.f16.f16.f16.f16 "
        "{%0,%1}, {%2,%3}, {%4}, {%5,%6};"
        : "=r"(d[0]), "=r"(d[1])
        : "r"(a0), "r"(a1), "r"(b0), "r"(0u), "r"(0u));
}
// MMA2: m16n8k16 f16, f32 accumulate
__device__ __forceinline__ void mma_k16(float* c, uint32_t a0, uint32_t a1,
                                        uint32_t a2, uint32_t a3,
                                        uint32_t b0, uint32_t b1) {
    asm volatile(
        "mma.sync.aligned.m16n8k16.row.col.f32.f16.f16.f32 "
        "{%0,%1,%2,%3}, {%4,%5,%6,%7}, {%8,%9}, {%0,%1,%2,%3};"
        : "+f"(c[0]), "+f"(c[1]), "+f"(c[2]), "+f"(c[3])
        : "r"(a0), "r"(a1), "r"(a2), "r"(a3), "r"(b0), "r"(b1));
}

// ---------------------------------------------------------------------------
// Fused projection kernel — same math as R8, now 128 CTAs x 512 threads
// (single balanced wave on 148 SMs).
// ---------------------------------------------------------------------------
__global__ void __launch_bounds__(512) proj_fused_kernel(
        const float* __restrict__ x, const float* __restrict__ w_theta,
        const float* __restrict__ w_phi, const float* __restrict__ w_g) {
    __shared__ ull wt2[CH * 4];
    __shared__ ull wp2[CH * 4];
    __shared__ ull wg2[CH * 16];
    int tid = threadIdx.x;
    for (int i = tid; i < CH * 4; i += 512) {
        int kp = i & 3, c = i >> 2;
        wt2[i] = pk2(w_theta[(2 * kp) * CH + c] * 1.4426950408889634f,
                     w_theta[(2 * kp + 1) * CH + c] * 1.4426950408889634f);
        wp2[i] = pk2(w_phi[(2 * kp) * CH + c], w_phi[(2 * kp + 1) * CH + c]);
    }
    for (int i = tid; i < CH * 16; i += 512) {
        int jp = i & 15, c = i >> 4;
        wg2[i] = pk2(w_g[(2 * jp) * CH + c], w_g[(2 * jp + 1) * CH + c]);
    }
    __syncthreads();

    int bid = blockIdx.x;
    int n = bid >> 3, yt = bid & 7;
    int b0 = tid & 1, b1 = (tid >> 1) & 1;
    int xpair = (tid >> 2) & 31;
    int yp = tid >> 7;                 // 0..3
    int y = yt * 8 + yp * 2 + b1;
    int xc = xpair * 2 + b0;
    int l = y * 64 + xc;

    const float* xp = x + ((size_t)n * CH) * LL + l;

    ull at[4], ap[4], ag[16];
#pragma unroll
    for (int i = 0; i < 4; i++) { at[i] = 0ull; ap[i] = 0ull; }
#pragma unroll
    for (int i = 0; i < 16; i++) ag[i] = 0ull;

#pragma unroll 8
    for (int c = 0; c < CH; c++) {
        float xv = xp[(size_t)c * LL];
        ull vd = pk2(xv, xv);
#pragma unroll
        for (int kp = 0; kp < 4; kp++) at[kp] = fma2(wt2[c * 4 + kp], vd, at[kp]);
#pragma unroll
        for (int kp = 0; kp < 4; kp++) ap[kp] = fma2(wp2[c * 4 + kp], vd, ap[kp]);
#pragma unroll
        for (int jp = 0; jp < 16; jp++) ag[jp] = fma2(wg2[c * 16 + jp], vd, ag[jp]);
    }

    {
        float2 t0 = upk2(at[0]), t1 = upk2(at[1]), t2 = upk2(at[2]), t3 = upk2(at[3]);
        uint4 tq;
        tq.x = pack_h2(t0.x, t0.y);
        tq.y = pack_h2(t1.x, t1.y);
        tq.z = pack_h2(t2.x, t2.y);
        tq.w = pack_h2(t3.x, t3.y);
        *(uint4*)(g_thetaH + ((size_t)n * LL + l) * 4) = tq;
    }

    float phv[CK], gv[CG];
#pragma unroll
    for (int kp = 0; kp < 4; kp++) {
        float2 v = upk2(ap[kp]); phv[2 * kp] = v.x; phv[2 * kp + 1] = v.y;
    }
#pragma unroll
    for (int jp = 0; jp < 16; jp++) {
        float2 v = upk2(ag[jp]); gv[2 * jp] = v.x; gv[2 * jp + 1] = v.y;
    }
#pragma unroll
    for (int k = 0; k < CK; k++) {
        float v = phv[k];
        v = fmaxf(v, __shfl_xor_sync(0xffffffffu, v, 1));
        v = fmaxf(v, __shfl_xor_sync(0xffffffffu, v, 2));
        phv[k] = v;
    }
#pragma unroll
    for (int j = 0; j < CG; j++) {
        float v = gv[j];
        v = fmaxf(v, __shfl_xor_sync(0xffffffffu, v, 1));
        v = fmaxf(v, __shfl_xor_sync(0xffffffffu, v, 2));
        gv[j] = v;
    }

    if ((tid & 3) == 0) {
        int d = (yt * 4 + yp) * 32 + xpair;
        int s = d >> 4, gr = d & 7, u = (d >> 3) & 1;
        uint32_t* pdst = g_phiP + (size_t)n * 4096 + s * 64 + gr * 8 + u;
        pdst[0] = pack_h2(phv[0], phv[1]);
        pdst[2] = pack_h2(phv[2], phv[3]);
        pdst[4] = pack_h2(phv[4], phv[5]);
        pdst[6] = pack_h2(phv[6], phv[7]);

        int xu = (xpair >> 3) & 1;
        int qf = (xpair & 7) >> 1;
        int rb = xpair & 1;
        int elem = xu * 2 + rb;
        __half* gdst = g_gH + (size_t)n * CG * 1024;
#pragma unroll
        for (int j = 0; j < CG; j++)
            gdst[(j * 256 + s * 4 + qf) * 4 + elem] = __float2half_rn(gv[j]);
    }
}

// ---------------------------------------------------------------------------
// Attention kernel: tensor-core flash, M=32 per warp. Row sums moved OFF the
// tensor pipe (f16x2 adds on fma pipe, f32 flush every 8 iters, quad reduce)
// => 8 MMA2s per iter instead of 10.
// Grid (8 L-tiles, 16 n) x 512 threads = 128 CTAs, single wave.
// smem: phi 16K | gA 32.5K | gB 32.5K | wof 5K = 88064 B
// ---------------------------------------------------------------------------
#define SM_PHI 0
#define SM_GA  16384
#define SM_GB  49664
#define SM_WOF 82944
#define SMEM_SZ 88064

__global__ void __launch_bounds__(512, 1) attn_kernel(
        const float* __restrict__ x, const float* __restrict__ w_o,
        const float* __restrict__ gammap, float* __restrict__ out) {
    extern __shared__ char smem[];
    uint32_t* wof = (uint32_t*)(smem + SM_WOF);

    int tid = threadIdx.x;
    int n = blockIdx.y;
    int l0 = blockIdx.x * 512;
    float gamma = *gammap;

    // Cooperative fills
    {
        const uint4* s1 = (const uint4*)(g_phiP + (size_t)n * 4096);
        uint4* d1 = (uint4*)(smem + SM_PHI);
        for (int i = tid; i < 1024; i += 512) d1[i] = s1[i];
        const ull* s2 = (const ull*)(g_gH + (size_t)n * CG * 1024);
        ull* gA = (ull*)(smem + SM_GA);
        ull* gB = (ull*)(smem + SM_GB);
        for (int i = tid; i < 8192; i += 512) {
            ull v = s2[i];
            int j = i >> 8, sq = i & 255;
            int gr = j & 7, half = (j >> 3) & 1;
            ull* arr = (j < 16) ? gA : gB;
            arr[(gr * 260 + sq) * 2 + half] = v;
        }
        const float2* s3 = (const float2*)w_o;
        for (int i = tid; i < 1024; i += 512) {
            int oc = i >> 4, kq = i & 15;
            float2 w = s3[oc * 16 + kq];
            wof[oc * 20 + kq] = pack_h2(w.x * gamma, w.y * gamma);
        }
    }

    int warp = tid >> 5, lane = tid & 31;
    int gr = lane >> 2, q = lane & 3;
    int rXa = warp * 32 + gr;     // X block rows: rXa, rXa+8
    int rYa = rXa + 16;           // Y block rows: rYa, rYa+8

    const uint32_t* tbase = g_thetaH + ((size_t)n * LL + l0) * 4 + q;
    uint32_t tXa = tbase[(size_t)rXa * 4];
    uint32_t tXb = tbase[(size_t)(rXa + 8) * 4];
    uint32_t tYa = tbase[(size_t)rYa * 4];
    uint32_t tYb = tbase[(size_t)(rYa + 8) * 4];
    __syncthreads();

    float c0[4], c1[4], c2[4], c3[4];   // X accumulators
    float d0[4], d1[4], d2a[4], d3[4];  // Y accumulators
#pragma unroll
    for (int i = 0; i < 4; i++) {
        c0[i] = 0.f; c1[i] = 0.f; c2[i] = 0.f; c3[i] = 0.f;
        d0[i] = 0.f; d1[i] = 0.f; d2a[i] = 0.f; d3[i] = 0.f;
    }
    // row-sum accumulators: f32 master + f16x2 short-horizon
    float sX0 = 0.f, sX1 = 0.f, sY0 = 0.f, sY1 = 0.f;

    const char* phiPtr = smem + SM_PHI + (gr * 8 + q * 2) * 4;
    const char* gaPtr  = smem + SM_GA + (gr * 260 + q) * 16;
    const char* gbPtr  = smem + SM_GB + (gr * 260 + q) * 16;

    // --- pipeline preamble: logits+exp for s=0, g for s=0 ---
    uint32_t aq0, aq1, aq2, aq3, aq4, aq5, aq6, aq7;
    {
        ull pv0 = *(const ull*)phiPtr;
        uint32_t h0[2], h1[2], h2[2], h3[2];
        mma_k8_h(h0, tXa, tXb, (uint32_t)pv0);
        mma_k8_h(h1, tXa, tXb, (uint32_t)(pv0 >> 32));
        mma_k8_h(h2, tYa, tYb, (uint32_t)pv0);
        mma_k8_h(h3, tYa, tYb, (uint32_t)(pv0 >> 32));
        aq0 = ex2h2(h0[0]); aq1 = ex2h2(h0[1]);
        aq2 = ex2h2(h1[0]); aq3 = ex2h2(h1[1]);
        aq4 = ex2h2(h2[0]); aq5 = ex2h2(h2[1]);
        aq6 = ex2h2(h3[0]); aq7 = ex2h2(h3[1]);
    }
    ulonglong2 ga = *(const ulonglong2*)gaPtr;
    ulonglong2 gb = *(const ulonglong2*)gbPtr;

#pragma unroll 1
    for (int s0 = 0; s0 < 64; s0 += 8) {
        uint32_t hX0 = 0u, hX1 = 0u, hY0 = 0u, hY1 = 0u;   // f16x2 {0,0}
#pragma unroll
        for (int si = 0; si < 8; si++) {
            // ---- stage A(s+1): logits (last iter overreads into gA: discarded) ----
            phiPtr += 256;
            ull pvn = *(const ull*)phiPtr;
            uint32_t h0[2], h1[2], h2[2], h3[2];
            mma_k8_h(h0, tXa, tXb, (uint32_t)pvn);
            mma_k8_h(h1, tXa, tXb, (uint32_t)(pvn >> 32));
            mma_k8_h(h2, tYa, tYb, (uint32_t)pvn);
            mma_k8_h(h3, tYa, tYb, (uint32_t)(pvn >> 32));

            gaPtr += 64; gbPtr += 64;
            ulonglong2 gan = *(const ulonglong2*)gaPtr;
            ulonglong2 gbn = *(const ulonglong2*)gbPtr;

            // ---- stage B(s): MMA2 batch (8 MMAs, tensor pipe) ----
            mma_k16(c0, aq0, aq1, aq2, aq3, (uint32_t)ga.x, (uint32_t)(ga.x >> 32));
            mma_k16(c1, aq0, aq1, aq2, aq3, (uint32_t)ga.y, (uint32_t)(ga.y >> 32));
            mma_k16(c2, aq0, aq1, aq2, aq3, (uint32_t)gb.x, (uint32_t)(gb.x >> 32));
            mma_k16(c3, aq0, aq1, aq2, aq3, (uint32_t)gb.y, (uint32_t)(gb.y >> 32));
            mma_k16(d0, aq4, aq5, aq6, aq7, (uint32_t)ga.x, (uint32_t)(ga.x >> 32));
            mma_k16(d1, aq4, aq5, aq6, aq7, (uint32_t)ga.y, (uint32_t)(ga.y >> 32));
            mma_k16(d2a, aq4, aq5, aq6, aq7, (uint32_t)gb.x, (uint32_t)(gb.x >> 32));
            mma_k16(d3, aq4, aq5, aq6, aq7, (uint32_t)gb.y, (uint32_t)(gb.y >> 32));

            // ---- row sums of a(s) on the fma pipe (f16x2) ----
            hX0 = hadd2u(hX0, hadd2u(aq0, aq2));   // row rXa
            hX1 = hadd2u(hX1, hadd2u(aq1, aq3));   // row rXa+8
            hY0 = hadd2u(hY0, hadd2u(aq4, aq6));   // row rYa
            hY1 = hadd2u(hY1, hadd2u(aq5, aq7));   // row rYa+8

            // ---- exp for s+1 (MUFU, overlaps MMA2 drain) ----
            aq0 = ex2h2(h0[0]); aq1 = ex2h2(h0[1]);
            aq2 = ex2h2(h1[0]); aq3 = ex2h2(h1[1]);
            aq4 = ex2h2(h2[0]); aq5 = ex2h2(h2[1]);
            aq6 = ex2h2(h3[0]); aq7 = ex2h2(h3[1]);

            ga = gan; gb = gbn;
        }
        // flush f16 partials to f32 (bounds accumulation error)
        sX0 += h2sum(hX0); sX1 += h2sum(hX1);
        sY0 += h2sum(hY0); sY1 += h2sum(hY1);
    }

    // complete row sums across the quad (each thread held 4 of 16 columns/chunk)
    sX0 += __shfl_xor_sync(0xffffffffu, sX0, 1);
    sX0 += __shfl_xor_sync(0xffffffffu, sX0, 2);
    sX1 += __shfl_xor_sync(0xffffffffu, sX1, 1);
    sX1 += __shfl_xor_sync(0xffffffffu, sX1, 2);
    sY0 += __shfl_xor_sync(0xffffffffu, sY0, 1);
    sY0 += __shfl_xor_sync(0xffffffffu, sY0, 2);
    sY1 += __shfl_xor_sync(0xffffffffu, sY1, 1);
    sY1 += __shfl_xor_sync(0xffffffffu, sY1, 2);

    float invXa = 1.0f / sX0, invXb = 1.0f / sX1;
    float invYa = 1.0f / sY0, invYb = 1.0f / sY1;

    // epilogue A-fragments (k = j), X then Y
    uint32_t eX0 = pack_h2(c0[0] * invXa, c0[1] * invXa);
    uint32_t eX1 = pack_h2(c0[2] * invXb, c0[3] * invXb);
    uint32_t eX2 = pack_h2(c1[0] * invXa, c1[1] * invXa);
    uint32_t eX3 = pack_h2(c1[2] * invXb, c1[3] * invXb);
    uint32_t eX4 = pack_h2(c2[0] * invXa, c2[1] * invXa);
    uint32_t eX5 = pack_h2(c2[2] * invXb, c2[3] * invXb);
    uint32_t eX6 = pack_h2(c3[0] * invXa, c3[1] * invXa);
    uint32_t eX7 = pack_h2(c3[2] * invXb, c3[3] * invXb);
    uint32_t eY0 = pack_h2(d0[0] * invYa, d0[1] * invYa);
    uint32_t eY1 = pack_h2(d0[2] * invYb, d0[3] * invYb);
    uint32_t eY2 = pack_h2(d1[0] * invYa, d1[1] * invYa);
    uint32_t eY3 = pack_h2(d1[2] * invYb, d1[3] * invYb);
    uint32_t eY4 = pack_h2(d2a[0] * invYa, d2a[1] * invYa);
    uint32_t eY5 = pack_h2(d2a[2] * invYb, d2a[3] * invYb);
    uint32_t eY6 = pack_h2(d3[0] * invYa, d3[1] * invYa);
    uint32_t eY7 = pack_h2(d3[2] * invYb, d3[3] * invYb);

    const uint32_t* wrow = wof + gr * 20;
#pragma unroll
    for (int ob = 0; ob < 8; ob++) {
        uint32_t b00 = wrow[ob * 160 + q];
        uint32_t b01 = wrow[ob * 160 + q + 4];
        uint32_t b10 = wrow[ob * 160 + q + 8];
        uint32_t b11 = wrow[ob * 160 + q + 12];

        float fX[4] = {0.f, 0.f, 0.f, 0.f};
        mma_k16(fX, eX0, eX1, eX2, eX3, b00, b01);
        mma_k16(fX, eX4, eX5, eX6, eX7, b10, b11);
        float fY[4] = {0.f, 0.f, 0.f, 0.f};
        mma_k16(fY, eY0, eY1, eY2, eY3, b00, b01);
        mma_k16(fY, eY4, eY5, eY6, eY7, b10, b11);

        int oc = ob * 8 + 2 * q;
        const float* px = x + ((size_t)n * CH + oc) * LL + l0 + rXa;
        float* po = out + ((size_t)n * CH + oc) * LL + l0 + rXa;
        po[0]       = px[0]       + fX[0];
        po[LL]      = px[LL]      + fX[1];
        po[8]       = px[8]       + fX[2];
        po[LL + 8]  = px[LL + 8]  + fX[3];
        po[16]      = px[16]      + fY[0];
        po[LL + 16] = px[LL + 16] + fY[1];
        po[24]      = px[24]      + fY[2];
        po[LL + 24] = px[LL + 24] + fY[3];
    }
}

// ---------------------------------------------------------------------------
extern "C" void kernel_launch(void* const* d_in, const int* in_sizes, int n_in,
                              void* d_out, int out_size) {
    const float* x       = (const float*)d_in[0];
    const float* w_theta = (const float*)d_in[1];
    const float* w_phi   = (const float*)d_in[2];
    const float* w_g     = (const float*)d_in[3];
    const float* w_o     = (const float*)d_in[4];
    const float* gammap  = (const float*)d_in[5];
    float* out = (float*)d_out;

    cudaFuncSetAttribute(attn_kernel, cudaFuncAttributeMaxDynamicSharedMemorySize,
                         SMEM_SZ);

    proj_fused_kernel<<<NB * 8, 512>>>(x, w_theta, w_phi, w_g);
    dim3 grid(8, NB);
    attn_kernel<<<grid, 512, SMEM_SZ>>>(x, w_o, gammap, out);
}